// round 13
// baseline (speedup 1.0000x reference)
#include <cuda_runtime.h>
#include <math.h>

#define BN 16
#define HH 480
#define WW 640
#define HW (HH * WW)
#define HW4 (HW / 4)            // 76800 float4 per plane
#define W4 (WW / 4)             // 160 float4 per row
#define GX 37
#define TPB 256
#define NBLK (GX * BN)          // 592 = 148 SMs * 4 CTAs, single balanced wave
#define STRIDE4 (GX * TPB)      // 9472
#define MAIN_ITERS 8            // 8*9472 = 75776 quads per plane
#define MAIN_Q (MAIN_ITERS * STRIDE4)
#define TAIL_Q (HW4 - MAIN_Q)   // 1024 quads per plane
#define TAIL_TOTAL (BN * TAIL_Q) // 16384

// Allocation-free scratch.
__device__ double g_acc = 0.0;
__device__ unsigned int g_count = 0;

// L2-only load (bypass L1 allocate): streams are read exactly once.
__device__ __forceinline__ float4 ldcg4(const float4* p) {
    return __ldcg(p);
}

// Exact GELU, fast path: for |z| >= 16, z*Phi(z) == max(z,0) to <1e-50 abs.
__device__ __forceinline__ float gelu_exact(float z) {
    float val = fmaxf(z, 0.0f);
    if (fabsf(z) < 16.0f) val = z * normcdff(z);
    return val;
}

__device__ __forceinline__ float quad_sum(
    float4 g0, float4 g1, float4 n0, float4 n1, int i,
    float V0, float V1, float V2, float O0, float O1, float O2)
{
    const int   h  = i / W4;                 // const divisor -> mul/shift
    const float x0 = (float)((i - h * W4) * 4);
    const float y  = (float)h;

    const float AV1    = fmaf(y, V2, -V1);          // -V1 + y*V2
    const float yO2    = y * O2;
    const float y2p1O0 = fmaf(y, y, 1.0f) * O0;     // (y^2+1)*O0
    const float yO0    = y * O0;
    const float yO1    = y * O1;

    const float* ga = &g0.x;
    const float* gb = &g1.x;
    const float* na = &n0.x;
    const float* nb = &n1.x;

    float s4 = 0.0f;
    #pragma unroll
    for (int j = 0; j < 4; j++) {
        const float x = x0 + (float)j;

        const float AV0 = fmaf(x, V2, -V0);                        // -V0 + x*V2
        // BW0 = x*(y*O0) - (x^2+1)*O1 + y*O2
        const float BW0 = fmaf(x, yO0, fmaf(-fmaf(x, x, 1.0f), O1, yO2));
        // BW1 = (y^2+1)*O0 - x*(y*O1) - x*O2
        const float BW1 = fmaf(-x, yO1, fmaf(-x, O2, y2p1O0));

        const float gg0 = ga[j], gg1 = gb[j];
        const float s = fmaf(gg0, AV0, gg1 * AV1);
        const float t = (na[j] + nb[j]) - fmaf(gg0, BW0, gg1 * BW1);
        s4 += gelu_exact(-(s * t));
    }
    return s4;
}

__global__ __launch_bounds__(TPB, 4) void cheirality_fused(
    const float* __restrict__ pose,
    const float* __restrict__ grad,
    const float* __restrict__ nf,
    float* __restrict__ out)
{
    const int b   = blockIdx.y;
    const int tid = threadIdx.x;

    const float V0 = __ldg(pose + b * 6 + 0);
    const float V1 = __ldg(pose + b * 6 + 1);
    const float V2 = __ldg(pose + b * 6 + 2);
    const float O0 = __ldg(pose + b * 6 + 3);
    const float O1 = __ldg(pose + b * 6 + 4);
    const float O2 = __ldg(pose + b * 6 + 5);

    const float4* __restrict__ g0p = (const float4*)(grad + (size_t)b * 2 * HW);
    const float4* __restrict__ g1p = g0p + HW4;
    const float4* __restrict__ n0p = (const float4*)(nf + (size_t)b * 2 * HW);
    const float4* __restrict__ n1p = n0p + HW4;

    const int i0 = blockIdx.x * TPB + tid;   // 0..9471

    float acc = 0.0f;

    // ---- main loop: exactly 8 pipelined, fully unrolled iterations ----
    int i = i0;
    float4 g0 = ldcg4(g0p + i), g1 = ldcg4(g1p + i);
    float4 n0 = ldcg4(n0p + i), n1 = ldcg4(n1p + i);

    #pragma unroll
    for (int k = 1; k < MAIN_ITERS; k++) {
        const int inext = i0 + k * STRIDE4;
        float4 g0n = ldcg4(g0p + inext);
        float4 g1n = ldcg4(g1p + inext);
        float4 n0n = ldcg4(n0p + inext);
        float4 n1n = ldcg4(n1p + inext);

        acc += quad_sum(g0, g1, n0, n1, i, V0, V1, V2, O0, O1, O2);

        i = inext;
        g0 = g0n; g1 = g1n; n0 = n0n; n1 = n1n;
    }
    acc += quad_sum(g0, g1, n0, n1, i, V0, V1, V2, O0, O1, O2);

    // ---- distributed tail: 16384 leftover quads, flat thread ids 0..16383 ----
    const int ft = (b * GX + blockIdx.x) * TPB + tid;
    if (ft < TAIL_TOTAL) {
        const int tb = ft / TAIL_Q;                  // plane (const divisor)
        const int ti = MAIN_Q + (ft - tb * TAIL_Q);  // quad index in plane

        const float4* __restrict__ tg = (const float4*)(grad + (size_t)tb * 2 * HW);
        const float4* __restrict__ tn = (const float4*)(nf   + (size_t)tb * 2 * HW);
        float4 tg0 = ldcg4(tg + ti), tg1 = ldcg4(tg + ti + HW4);
        float4 tn0 = ldcg4(tn + ti), tn1 = ldcg4(tn + ti + HW4);

        const float tV0 = __ldg(pose + tb * 6 + 0);
        const float tV1 = __ldg(pose + tb * 6 + 1);
        const float tV2 = __ldg(pose + tb * 6 + 2);
        const float tO0 = __ldg(pose + tb * 6 + 3);
        const float tO1 = __ldg(pose + tb * 6 + 4);
        const float tO2 = __ldg(pose + tb * 6 + 5);

        acc += quad_sum(tg0, tg1, tn0, tn1, ti, tV0, tV1, tV2, tO0, tO1, tO2);
    }

    // ---- block reduction (float tree) ----
    __shared__ float warp_sums[TPB / 32];
    const unsigned mask = 0xFFFFFFFFu;
    #pragma unroll
    for (int off = 16; off > 0; off >>= 1)
        acc += __shfl_down_sync(mask, acc, off);

    const int lane = tid & 31;
    const int wid  = tid >> 5;
    if (lane == 0) warp_sums[wid] = acc;
    __syncthreads();

    // ---- atomic tail: per-block double add + fence-ordered counter ----
    if (tid == 0) {
        float bsum = 0.0f;
        #pragma unroll
        for (int w = 0; w < TPB / 32; w++) bsum += warp_sums[w];

        atomicAdd(&g_acc, (double)bsum);
        __threadfence();
        const unsigned int old = atomicAdd(&g_count, 1u);
        if (old == (unsigned)(NBLK - 1)) {
            __threadfence();
            const double total = g_acc;
            out[0] = (float)(total / (double)((long long)BN * HW));
            // reset for the next graph replay
            g_acc = 0.0;
            __threadfence();
            g_count = 0;
        }
    }
}

extern "C" void kernel_launch(void* const* d_in, const int* in_sizes, int n_in,
                              void* d_out, int out_size) {
    const float* pose = (const float*)d_in[0];
    const float* grad = (const float*)d_in[1];
    const float* nf   = (const float*)d_in[2];
    float* out = (float*)d_out;

    dim3 grid(GX, BN);
    cheirality_fused<<<grid, TPB>>>(pose, grad, nf, out);
}

// round 14
// speedup vs baseline: 1.1571x; 1.1571x over previous
#include <cuda_runtime.h>
#include <math.h>

#define BN 16
#define HH 480
#define WW 640
#define HW (HH * WW)
#define HW4 (HW / 4)            // 76800 float4 per plane
#define W4 (WW / 4)             // 160 float4 per row
#define GX 37
#define TPB 256
#define NBLK (GX * BN)          // 592 = 148 SMs * 4 CTAs, single balanced wave
#define STRIDE4 (GX * TPB)      // 9472
#define MAIN_ITERS 8            // 8*9472 = 75776 quads per plane
#define MAIN_Q (MAIN_ITERS * STRIDE4)
#define TAIL_Q (HW4 - MAIN_Q)   // 1024 quads per plane
#define TAIL_TOTAL (BN * TAIL_Q) // 16384

// Allocation-free scratch.
__device__ double g_acc = 0.0;
__device__ unsigned int g_count = 0;

// Exact GELU, fast path: for |z| >= 16, z*Phi(z) == max(z,0) to <1e-50 abs.
__device__ __forceinline__ float gelu_exact(float z) {
    float val = fmaxf(z, 0.0f);
    if (fabsf(z) < 16.0f) val = z * normcdff(z);
    return val;
}

__device__ __forceinline__ float quad_sum(
    float4 g0, float4 g1, float4 n0, float4 n1, int i,
    float V0, float V1, float V2, float O0, float O1, float O2)
{
    const int   h  = i / W4;                 // const divisor -> mul/shift
    const float x0 = (float)((i - h * W4) * 4);
    const float y  = (float)h;

    const float AV1    = fmaf(y, V2, -V1);          // -V1 + y*V2
    const float yO2    = y * O2;
    const float y2p1O0 = fmaf(y, y, 1.0f) * O0;     // (y^2+1)*O0
    const float yO0    = y * O0;
    const float yO1    = y * O1;

    const float* ga = &g0.x;
    const float* gb = &g1.x;
    const float* na = &n0.x;
    const float* nb = &n1.x;

    float s4 = 0.0f;
    #pragma unroll
    for (int j = 0; j < 4; j++) {
        const float x = x0 + (float)j;

        const float AV0 = fmaf(x, V2, -V0);                        // -V0 + x*V2
        // BW0 = x*(y*O0) - (x^2+1)*O1 + y*O2
        const float BW0 = fmaf(x, yO0, fmaf(-fmaf(x, x, 1.0f), O1, yO2));
        // BW1 = (y^2+1)*O0 - x*(y*O1) - x*O2
        const float BW1 = fmaf(-x, yO1, fmaf(-x, O2, y2p1O0));

        const float gg0 = ga[j], gg1 = gb[j];
        const float s = fmaf(gg0, AV0, gg1 * AV1);
        const float t = (na[j] + nb[j]) - fmaf(gg0, BW0, gg1 * BW1);
        s4 += gelu_exact(-(s * t));
    }
    return s4;
}

__global__ __launch_bounds__(TPB, 4) void cheirality_fused(
    const float* __restrict__ pose,
    const float* __restrict__ grad,
    const float* __restrict__ nf,
    float* __restrict__ out)
{
    const int b   = blockIdx.y;
    const int tid = threadIdx.x;

    const float V0 = __ldg(pose + b * 6 + 0);
    const float V1 = __ldg(pose + b * 6 + 1);
    const float V2 = __ldg(pose + b * 6 + 2);
    const float O0 = __ldg(pose + b * 6 + 3);
    const float O1 = __ldg(pose + b * 6 + 4);
    const float O2 = __ldg(pose + b * 6 + 5);

    const float4* __restrict__ g0p = (const float4*)(grad + (size_t)b * 2 * HW);
    const float4* __restrict__ g1p = g0p + HW4;
    const float4* __restrict__ n0p = (const float4*)(nf + (size_t)b * 2 * HW);
    const float4* __restrict__ n1p = n0p + HW4;

    const int i0 = blockIdx.x * TPB + tid;   // 0..9471

    float acc = 0.0f;

    // ---- main loop: exactly 8 pipelined, fully unrolled iterations ----
    int i = i0;
    float4 g0 = g0p[i], g1 = g1p[i], n0 = n0p[i], n1 = n1p[i];

    #pragma unroll
    for (int k = 1; k < MAIN_ITERS; k++) {
        const int inext = i0 + k * STRIDE4;
        float4 g0n = g0p[inext];
        float4 g1n = g1p[inext];
        float4 n0n = n0p[inext];
        float4 n1n = n1p[inext];

        acc += quad_sum(g0, g1, n0, n1, i, V0, V1, V2, O0, O1, O2);

        i = inext;
        g0 = g0n; g1 = g1n; n0 = n0n; n1 = n1n;
    }
    acc += quad_sum(g0, g1, n0, n1, i, V0, V1, V2, O0, O1, O2);

    // ---- distributed tail: 16384 leftover quads, flat thread ids 0..16383 ----
    const int ft = (b * GX + blockIdx.x) * TPB + tid;
    if (ft < TAIL_TOTAL) {
        const int tb = ft / TAIL_Q;                  // plane (const divisor)
        const int ti = MAIN_Q + (ft - tb * TAIL_Q);  // quad index in plane

        const float4* __restrict__ tg = (const float4*)(grad + (size_t)tb * 2 * HW);
        const float4* __restrict__ tn = (const float4*)(nf   + (size_t)tb * 2 * HW);
        float4 tg0 = tg[ti], tg1 = tg[ti + HW4];
        float4 tn0 = tn[ti], tn1 = tn[ti + HW4];

        const float tV0 = __ldg(pose + tb * 6 + 0);
        const float tV1 = __ldg(pose + tb * 6 + 1);
        const float tV2 = __ldg(pose + tb * 6 + 2);
        const float tO0 = __ldg(pose + tb * 6 + 3);
        const float tO1 = __ldg(pose + tb * 6 + 4);
        const float tO2 = __ldg(pose + tb * 6 + 5);

        acc += quad_sum(tg0, tg1, tn0, tn1, ti, tV0, tV1, tV2, tO0, tO1, tO2);
    }

    // ---- block reduction (float tree) ----
    __shared__ float warp_sums[TPB / 32];
    const unsigned mask = 0xFFFFFFFFu;
    #pragma unroll
    for (int off = 16; off > 0; off >>= 1)
        acc += __shfl_down_sync(mask, acc, off);

    const int lane = tid & 31;
    const int wid  = tid >> 5;
    if (lane == 0) warp_sums[wid] = acc;
    __syncthreads();

    // ---- atomic tail: per-block double add + fence-ordered counter.
    //      The block observing count==NBLK-1 knows every add is visible. ----
    if (tid == 0) {
        float bsum = 0.0f;
        #pragma unroll
        for (int w = 0; w < TPB / 32; w++) bsum += warp_sums[w];

        atomicAdd(&g_acc, (double)bsum);
        __threadfence();
        const unsigned int old = atomicAdd(&g_count, 1u);
        if (old == (unsigned)(NBLK - 1)) {
            __threadfence();
            const double total = g_acc;
            out[0] = (float)(total / (double)((long long)BN * HW));
            // reset for the next graph replay
            g_acc = 0.0;
            __threadfence();
            g_count = 0;
        }
    }
}

extern "C" void kernel_launch(void* const* d_in, const int* in_sizes, int n_in,
                              void* d_out, int out_size) {
    const float* pose = (const float*)d_in[0];
    const float* grad = (const float*)d_in[1];
    const float* nf   = (const float*)d_in[2];
    float* out = (float*)d_out;

    dim3 grid(GX, BN);
    cheirality_fused<<<grid, TPB>>>(pose, grad, nf, out);
}